// round 9
// baseline (speedup 1.0000x reference)
#include <cuda_runtime.h>
#include <cuda_bf16.h>
#include <math.h>
#include <cstdint>

#define L_ 512
#define B_ 64
#define E_ 256
#define H_ 256
#define T_ 12
#define CS 8    // cluster size (verified working)

typedef unsigned long long u64;

// ---------------- helpers ----------------
__device__ __forceinline__ u64 fma2(u64 a, u64 b, u64 c) {
    u64 d;
    asm("fma.rn.f32x2 %0, %1, %2, %3;" : "=l"(d) : "l"(a), "l"(b), "l"(c));
    return d;
}
__device__ __forceinline__ float2 unpack2(u64 v) {
    float2 r;
    asm("mov.b64 {%0, %1}, %2;" : "=f"(r.x), "=f"(r.y) : "l"(v));
    return r;
}
__device__ __forceinline__ float tanhap(float x) {
    float y;
    asm("tanh.approx.f32 %0, %1;" : "=f"(y) : "f"(x));
    return y;
}
__device__ __forceinline__ float sigap(float x) {
    return fmaf(0.5f, tanhap(0.5f * x), 0.5f);
}
__device__ __forceinline__ float ex2f(float x) {
    float y;
    asm("ex2.approx.f32 %0, %1;" : "=f"(y) : "f"(x));
    return y;
}
__device__ __forceinline__ float lg2f(float x) {
    float y;
    asm("lg2.approx.f32 %0, %1;" : "=f"(y) : "f"(x));
    return y;
}
__device__ __forceinline__ uint32_t smem_u32(const void* p) {
    uint32_t a;
    asm("{ .reg .u64 t; cvta.to.shared.u64 t, %1; cvt.u32.u64 %0, t; }" : "=r"(a) : "l"(p));
    return a;
}
__device__ __forceinline__ uint32_t packbf(float lo, float hi) {
    uint32_t r;
    asm("cvt.rn.bf16x2.f32 %0, %1, %2;" : "=r"(r) : "f"(hi), "f"(lo));
    return r;
}
__device__ __forceinline__ void ldsm_x4(uint32_t& r0, uint32_t& r1, uint32_t& r2, uint32_t& r3, uint32_t addr) {
    asm volatile("ldmatrix.sync.aligned.m8n8.x4.shared.b16 {%0,%1,%2,%3}, [%4];"
        : "=r"(r0), "=r"(r1), "=r"(r2), "=r"(r3) : "r"(addr));
}
__device__ __forceinline__ void mma16816(float& d0, float& d1, float& d2, float& d3,
                                         uint32_t a0, uint32_t a1, uint32_t a2, uint32_t a3,
                                         uint32_t b0, uint32_t b1) {
    asm volatile("mma.sync.aligned.m16n8k16.row.col.f32.bf16.bf16.f32 "
        "{%0,%1,%2,%3}, {%4,%5,%6,%7}, {%8,%9}, {%0,%1,%2,%3};"
        : "+f"(d0), "+f"(d1), "+f"(d2), "+f"(d3)
        : "r"(a0), "r"(a1), "r"(a2), "r"(a3), "r"(b0), "r"(b1));
}
__device__ __forceinline__ uint32_t mapa_rank(uint32_t local, uint32_t rank) {
    uint32_t r;
    asm("mapa.shared::cluster.u32 %0, %1, %2;" : "=r"(r) : "r"(local), "r"(rank));
    return r;
}
__device__ __forceinline__ void stsc_v4(uint32_t addr, uint4 v) {
    asm volatile("st.shared::cluster.v4.b32 [%0], {%1,%2,%3,%4};"
        :: "r"(addr), "r"(v.x), "r"(v.y), "r"(v.z), "r"(v.w) : "memory");
}
__device__ __forceinline__ void mbar_arrive_remote(uint32_t remAddr) {
    asm volatile("mbarrier.arrive.release.cluster.shared::cluster.b64 _, [%0];"
                 :: "r"(remAddr) : "memory");
}
__device__ __forceinline__ void mbar_wait_cluster(uint32_t mbar, uint32_t parity) {
    uint32_t done = 0;
    while (!done) {
        asm volatile(
            "{\n\t.reg .pred p;\n\t"
            "mbarrier.try_wait.parity.acquire.cluster.shared::cta.b64 p, [%1], %2, 0x989680;\n\t"
            "selp.b32 %0, 1, 0, p;\n\t}"
            : "=r"(done) : "r"(mbar), "r"(parity) : "memory");
    }
}

// ---------------- scratch ----------------
__device__ float g_gx[(size_t)2*L_*1024*B_];          // input gates TRANSPOSED: [2][L][gate-row j][b]
__device__ __nv_bfloat16 g_hb[(size_t)2*L_*B_*H_];    // hidden bf16 (consumed only by k_emit)
__device__ float g_emit[(size_t)L_*B_*T_];
__device__ float g_nll[B_];

// ---------------- input-gate GEMM (f32x2 packed; transposed store; unchanged) ----------------
__global__ __launch_bounds__(256, 1) void k_ingate(
    const int* __restrict__ sent, const float* __restrict__ emb,
    const float* __restrict__ Wf, const float* __restrict__ bfv,
    const float* __restrict__ Wb, const float* __restrict__ bbv)
{
    extern __shared__ float Xs[];
    __shared__ int tok[B_];
    int l   = blockIdx.x;
    int tid = threadIdx.x;
    if (tid < B_) tok[tid] = sent[tid*L_ + l];
    __syncthreads();
    float4* Xs4 = (float4*)Xs;
    #pragma unroll
    for (int i = 0; i < 16; i++) {
        int e = i*256 + tid;
        int r = e >> 6, kq = e & 63;
        Xs4[e] = ((const float4*)emb)[(size_t)tok[r]*64 + kq];
    }
    __syncthreads();

    int j   = blockIdx.y*256 + tid;
    int dir = j >> 10, jj = j & 1023;
    const float* W = dir ? Wb : Wf;
    const ulonglong2* W2 = (const ulonglong2*)(W + (size_t)jj*256);
    const ulonglong2* X2 = (const ulonglong2*)Xs;

    u64 acc2[64];
    #pragma unroll
    for (int r = 0; r < 64; r++) acc2[r] = 0ull;

    #pragma unroll 1
    for (int k4 = 0; k4 < 64; k4++) {
        ulonglong2 w = W2[k4];
        #pragma unroll
        for (int r = 0; r < 64; r++) {
            ulonglong2 x = X2[r*64 + k4];
            acc2[r] = fma2(w.x, x.x, acc2[r]);
            acc2[r] = fma2(w.y, x.y, acc2[r]);
        }
    }
    float bias = (dir ? bbv : bfv)[jj];
    float* outp = g_gx + ((size_t)(dir*L_ + l)*1024 + jj)*64;
    #pragma unroll
    for (int r4 = 0; r4 < 16; r4++) {
        float2 pa = unpack2(acc2[4*r4+0]);
        float2 pb = unpack2(acc2[4*r4+1]);
        float2 pc = unpack2(acc2[4*r4+2]);
        float2 pd = unpack2(acc2[4*r4+3]);
        *(float4*)(outp + 4*r4) = make_float4(pa.x+pa.y+bias, pb.x+pb.y+bias,
                                              pc.x+pc.y+bias, pd.x+pd.y+bias);
    }
}

// ---------------- persistent LSTM: mma.sync + DSMEM h push (double-buffered B tiles) ----------------
// 32 CTAs = (dir 2) x (batch-half 2) x (rank 8). CTA owns hids [32p,32p+32), batches [32bh,32bh+32).
// Per step: wait -> mma on B[(s-1)&1] (peers pushed h directly) -> Ps(gx)+D -> act ->
//           transpose to Ts -> st.shared::cluster into all 8 peers' B[s&1] -> fence -> arrive.
static const int BS_PITCH_B = 528;                    // bytes per B-tile row (32 rows)
static const int BSZ        = 32 * BS_PITCH_B;        // 16896 per buffer
static const int SM_B0      = 0;
static const int SM_B1      = BSZ;                    // 16896
static const int SM_PS      = 2*BSZ;                  // 33792
static const int PS_PITCH   = 34;
static const int SM_TS      = SM_PS + 128*PS_PITCH*4; // 51200 (32 rows x 80 B)
static const int SM_MBAR    = SM_TS + 32*80;          // 53760
static const int LSTM_SMEM  = SM_MBAR + 128;

__global__ __launch_bounds__(256, 1) __cluster_dims__(CS, 1, 1)
void k_lstm(const float* __restrict__ Whf, const float* __restrict__ Whb)
{
    extern __shared__ __align__(1024) char sm[];
    float* Ps = (float*)(sm + SM_PS);
    uint32_t smb = smem_u32(sm);
    int d  = blockIdx.x >> 4;             // direction
    int bh = (blockIdx.x >> 3) & 1;       // batch half
    uint32_t p;
    asm("mov.u32 %0, %%cluster_ctarank;" : "=r"(p));
    int hb = (int)p * 32;
    int tid = threadIdx.x;
    int w = tid >> 5, l = tid & 31;
    const float* W = d ? Whb : Whf;

    // zero both B buffers (B[1] must be zero for step-0 MMA), init barriers
    for (int i = tid; i < 2*BSZ/4; i += 256) ((uint32_t*)sm)[i] = 0;
    if (tid == 0) {
        asm volatile("mbarrier.init.shared.b64 [%0], %1;" :: "r"(smb + SM_MBAR),     "r"((uint32_t)CS) : "memory");
        asm volatile("mbarrier.init.shared.b64 [%0], %1;" :: "r"(smb + SM_MBAR + 8), "r"((uint32_t)CS) : "memory");
    }
    __syncthreads();
    asm volatile("barrier.cluster.arrive.aligned;" ::: "memory");
    asm volatile("barrier.cluster.wait.aligned;" ::: "memory");

    // ---- A fragments: warp w -> m-rows [16w,16w+16), all 32 n ----
    int r0 = 16*w + (l >> 2), r1 = r0 + 8;
    const float* wr0 = W + (size_t)((r0 >> 5)*H_ + hb + (r0 & 31))*H_;
    const float* wr1 = W + (size_t)((r1 >> 5)*H_ + hb + (r1 & 31))*H_;
    uint32_t A0[16], A1[16], A2[16], A3[16];
    {
        int kc0 = (l & 3)*2;
        #pragma unroll
        for (int kt = 0; kt < 16; kt++) {
            int kc = kt*16 + kc0;
            A0[kt] = packbf(wr0[kc],   wr0[kc+1]);
            A1[kt] = packbf(wr1[kc],   wr1[kc+1]);
            A2[kt] = packbf(wr0[kc+8], wr0[kc+9]);
            A3[kt] = packbf(wr1[kc+8], wr1[kc+9]);
        }
    }

    // ldmatrix per-lane row base addresses (relative to B0)
    uint32_t rowa[4];
    {
        int lrow = l & 7, grp = l >> 3;
        #pragma unroll
        for (int nt = 0; nt < 4; nt++)
            rowa[nt] = smb + (uint32_t)((nt*8 + lrow)*BS_PITCH_B + grp*16);
    }

    // gx mapping
    int rr  = tid & 127;
    int bb0 = (tid >> 7) * 16;
    int goff = (rr >> 5)*256 + hb + (rr & 31);

    // phase-B mapping
    int hl = tid & 31, q = tid >> 5;
    float cst[4];
    #pragma unroll
    for (int k = 0; k < 4; k++) cst[k] = 0.f;

    // push mapping: thread -> (peer pr, row prow), 4 x 16B segments
    int pr   = tid & 7;
    int prow = (tid >> 3) & 31;
    uint32_t dst0 = mapa_rank(smb + SM_B0 + (uint32_t)(prow*BS_PITCH_B + hb*2), (uint32_t)pr);
    uint32_t dst1 = mapa_rank(smb + SM_B1 + (uint32_t)(prow*BS_PITCH_B + hb*2), (uint32_t)pr);
    uint32_t rem0 = 0, rem1 = 0;
    if (tid < CS) {
        rem0 = mapa_rank(smb + SM_MBAR,     (uint32_t)tid);
        rem1 = mapa_rank(smb + SM_MBAR + 8, (uint32_t)tid);
    }

    for (int s = 0; s < L_; s++) {
        int t = d ? (L_-1-s) : s;

        // gx prefetch (coalesced, independent of h)
        float4 gxv[4];
        {
            const float4* gxt = (const float4*)(g_gx + ((size_t)(d*L_ + t)*1024 + goff)*64 + 32*bh + bb0);
            #pragma unroll
            for (int j4 = 0; j4 < 4; j4++) gxv[j4] = gxt[j4];
        }

        if (s > 0) {
            int sp = s - 1;
            mbar_wait_cluster(smb + SM_MBAR + (sp & 1)*8, (uint32_t)((sp >> 1) & 1));
        }
        uint32_t boff = (uint32_t)(((s & 1) ^ 1) * BSZ);   // read B[(s-1)&1]

        // ---- MMA mainloop: D[128,32] ----
        float acc[4][4];
        #pragma unroll
        for (int nt = 0; nt < 4; nt++)
            #pragma unroll
            for (int k = 0; k < 4; k++) acc[nt][k] = 0.f;

        #pragma unroll
        for (int ktp = 0; ktp < 8; ktp++) {
            #pragma unroll
            for (int nt = 0; nt < 4; nt++) {
                uint32_t b0, b1, b2, b3;
                ldsm_x4(b0, b1, b2, b3, rowa[nt] + boff + ktp*64);
                mma16816(acc[nt][0], acc[nt][1], acc[nt][2], acc[nt][3],
                         A0[2*ktp], A1[2*ktp], A2[2*ktp], A3[2*ktp], b0, b1);
                mma16816(acc[nt][0], acc[nt][1], acc[nt][2], acc[nt][3],
                         A0[2*ktp+1], A1[2*ktp+1], A2[2*ktp+1], A3[2*ktp+1], b2, b3);
            }
        }

        // gx -> Ps
        {
            float2* prowp = (float2*)(Ps + rr*PS_PITCH + bb0);
            const float2* gv = (const float2*)gxv;
            #pragma unroll
            for (int j2 = 0; j2 < 8; j2++) prowp[j2] = gv[j2];
        }
        __syncthreads();

        // Ps += D
        {
            int cc = (l & 3)*2;
            #pragma unroll
            for (int nt = 0; nt < 4; nt++) {
                float2* p0 = (float2*)(Ps + r0*PS_PITCH + nt*8 + cc);
                float2 v0 = *p0; v0.x += acc[nt][0]; v0.y += acc[nt][1]; *p0 = v0;
                float2* p1 = (float2*)(Ps + r1*PS_PITCH + nt*8 + cc);
                float2 v1 = *p1; v1.x += acc[nt][2]; v1.y += acc[nt][3]; *p1 = v1;
            }
        }
        __syncthreads();

        // activations + c update
        float hout[4];
        #pragma unroll
        for (int j = 0; j < 2; j++) {
            float2 vi = *(const float2*)(Ps + (  0 + hl)*PS_PITCH + q*4 + 2*j);
            float2 vf = *(const float2*)(Ps + ( 32 + hl)*PS_PITCH + q*4 + 2*j);
            float2 vg = *(const float2*)(Ps + ( 64 + hl)*PS_PITCH + q*4 + 2*j);
            float2 vo = *(const float2*)(Ps + ( 96 + hl)*PS_PITCH + q*4 + 2*j);
            {
                float ig = sigap(vi.x), fg = sigap(vf.x), gg = tanhap(vg.x), og = sigap(vo.x);
                cst[2*j] = fg*cst[2*j] + ig*gg;
                hout[2*j] = og * tanhap(cst[2*j]);
            }
            {
                float ig = sigap(vi.y), fg = sigap(vf.y), gg = tanhap(vg.y), og = sigap(vo.y);
                cst[2*j+1] = fg*cst[2*j+1] + ig*gg;
                hout[2*j+1] = og * tanhap(cst[2*j+1]);
            }
        }
        // transpose to Ts[batch 32][hid 32 bf16] (pitch 80 B)
        {
            __nv_bfloat16* tsp = (__nv_bfloat16*)(sm + SM_TS);
            #pragma unroll
            for (int k = 0; k < 4; k++)
                tsp[(4*q + k)*40 + hl] = __float2bfloat16(hout[k]);
        }
        __syncthreads();

        if (s < L_-1) {
            // DSMEM push: my (row prow) 64B into peer pr's B[s&1] at column hb
            const uint4* tsr = (const uint4*)(sm + SM_TS + prow*80);
            uint32_t dst = (s & 1) ? dst1 : dst0;
            #pragma unroll
            for (int seg = 0; seg < 4; seg++) stsc_v4(dst + seg*16, tsr[seg]);
            asm volatile("fence.acq_rel.cluster;" ::: "memory");
            __syncthreads();
            if (tid < CS) mbar_arrive_remote((s & 1) ? rem1 : rem0);
        }

        // off-critical-path global h write for k_emit (one thread per row)
        if (pr == 0) {
            const uint4* tsr = (const uint4*)(sm + SM_TS + prow*80);
            uint4* gd = (uint4*)(g_hb + ((size_t)(d*L_ + t)*B_ + 32*bh + prow)*H_ + hb);
            #pragma unroll
            for (int seg = 0; seg < 4; seg++) gd[seg] = tsr[seg];
        }
    }
}

// ---------------- emission GEMM (reads bf16 h; unchanged) ----------------
__global__ __launch_bounds__(768) void k_emit(const float* __restrict__ Wem,
                                              const float* __restrict__ bem)
{
    extern __shared__ float smc[];
    float* Hcat = smc;            // [64][520]
    float* Wsm  = smc + 64*520;   // [12][516]
    int l   = blockIdx.x;
    int tid = threadIdx.x;
    const uint4* hf  = (const uint4*)(g_hb + ((size_t)0*L_ + l)*B_*H_);
    const uint4* hbk = (const uint4*)(g_hb + ((size_t)1*L_ + l)*B_*H_);
    for (int e = tid; e < 2048; e += 768) {
        int r = e >> 5, kq = e & 31;
        uint4 vf = hf[e], vb = hbk[e];
        const __nv_bfloat162* pf = (const __nv_bfloat162*)&vf;
        const __nv_bfloat162* pb = (const __nv_bfloat162*)&vb;
        float* df = Hcat + r*520 + kq*8;
        float* db = Hcat + r*520 + 256 + kq*8;
        #pragma unroll
        for (int qq = 0; qq < 4; qq++) {
            float2 f2 = __bfloat1622float2(pf[qq]);
            float2 b2 = __bfloat1622float2(pb[qq]);
            df[2*qq] = f2.x; df[2*qq+1] = f2.y;
            db[2*qq] = b2.x; db[2*qq+1] = b2.y;
        }
    }
    for (int e = tid; e < 12*512; e += 768)
        Wsm[(e >> 9)*516 + (e & 511)] = Wem[e];
    __syncthreads();

    int b = tid / 12, tg = tid - b*12;
    float acc = bem[tg];
    const float4* hrow = (const float4*)(Hcat + b*520);
    const float4* wrow = (const float4*)(Wsm + tg*516);
    #pragma unroll 8
    for (int k4 = 0; k4 < 128; k4++) {
        float4 x = hrow[k4]; float4 w = wrow[k4];
        acc += w.x*x.x + w.y*x.y + w.z*x.z + w.w*x.w;
    }
    g_emit[((size_t)l*B_ + b)*T_ + tg] = acc;
}

// ---------------- CRF NLL: base-2 domain, tree reductions, v[0]-referenced lse ----------------
__global__ void k_crf(const int* __restrict__ tags, const float* __restrict__ trans)
{
    int b = blockIdx.x;
    int lane = threadIdx.x;
    __shared__ float tr[T_*T_];
    for (int i = lane; i < T_*T_; i += 32) tr[i] = trans[i];
    __syncwarp();
    const unsigned FULL = 0xffffffffu;
    const float I2 = 1.4426950408889634f;
    const float LN2 = 0.6931471805599453f;
    int mylane = (lane < T_) ? lane : 0;
    float trr2[T_];
    #pragma unroll
    for (int t2 = 0; t2 < T_; t2++) trr2[t2] = tr[t2*T_ + mylane] * I2;

    float a2 = ((lane < T_) ? g_emit[(size_t)b*T_ + lane] : 0.f) * I2;
    float ep = (lane < T_) ? g_emit[((size_t)1*B_ + b)*T_ + lane] : 0.f;
    for (int l = 1; l < L_; l++) {
        float e2 = ep * I2;
        if (l + 1 < L_)
            ep = (lane < T_) ? g_emit[((size_t)(l+1)*B_ + b)*T_ + lane] : 0.f;
        float v[T_];
        #pragma unroll
        for (int t2 = 0; t2 < T_; t2++)
            v[t2] = __shfl_sync(FULL, a2, t2) + trr2[t2];
        float ex[T_];
        ex[0] = 1.0f;
        #pragma unroll
        for (int t2 = 1; t2 < T_; t2++) ex[t2] = ex2f(v[t2] - v[0]);
        float s01 = ex[0] + ex[1],  s23 = ex[2] + ex[3];
        float s45 = ex[4] + ex[5],  s67 = ex[6] + ex[7];
        float s89 = ex[8] + ex[9],  sAB = ex[10] + ex[11];
        float sA = (s01 + s23) + (s45 + s67);
        float ssum = sA + (s89 + sAB);
        a2 = v[0] + lg2f(ssum) + e2;
    }
    float am = (lane < T_) ? a2 : -1e30f;
    float mm = am;
    for (int o = 16; o; o >>= 1) mm = fmaxf(mm, __shfl_xor_sync(FULL, mm, o));
    float es = (lane < T_) ? ex2f(a2 - mm) : 0.f;
    for (int o = 16; o; o >>= 1) es += __shfl_xor_sync(FULL, es, o);
    float logZ = (mm + lg2f(es)) * LN2;

    float eg = 0.f, tg2 = 0.f;
    for (int l = lane; l < L_; l += 32) {
        int tv = tags[b*L_ + l];
        eg += g_emit[((size_t)l*B_ + b)*T_ + tv];
    }
    for (int l = lane; l < L_-1; l += 32) {
        int t0v = tags[b*L_ + l], t1v = tags[b*L_ + l + 1];
        tg2 += tr[t0v*T_ + t1v];
    }
    for (int o = 16; o; o >>= 1) {
        eg  += __shfl_xor_sync(FULL, eg,  o);
        tg2 += __shfl_xor_sync(FULL, tg2, o);
    }
    if (lane == 0) g_nll[b] = logZ - eg - tg2;
}

__global__ void k_mean(float* out)
{
    int lane = threadIdx.x;
    float s = (lane < 32) ? g_nll[lane] + g_nll[lane + 32] : 0.f;
    s += __shfl_xor_sync(0xffffffffu, s, 16);
    s += __shfl_xor_sync(0xffffffffu, s, 8);
    s += __shfl_xor_sync(0xffffffffu, s, 4);
    s += __shfl_xor_sync(0xffffffffu, s, 2);
    s += __shfl_xor_sync(0xffffffffu, s, 1);
    if (lane == 0) out[0] = s / (float)B_;
}

// ---------------- launch ----------------
extern "C" void kernel_launch(void* const* d_in, const int* in_sizes, int n_in,
                              void* d_out, int out_size)
{
    const int*   sent  = (const int*)  d_in[0];
    const int*   tags  = (const int*)  d_in[1];
    const float* emb   = (const float*)d_in[2];
    const float* Wihf  = (const float*)d_in[3];
    const float* Whhf  = (const float*)d_in[4];
    const float* bf    = (const float*)d_in[5];
    const float* Wihb  = (const float*)d_in[6];
    const float* Whhb  = (const float*)d_in[7];
    const float* bb    = (const float*)d_in[8];
    const float* Wem   = (const float*)d_in[9];
    const float* bem   = (const float*)d_in[10];
    const float* trans = (const float*)d_in[11];
    float* out = (float*)d_out;

    cudaFuncSetAttribute(k_ingate, cudaFuncAttributeMaxDynamicSharedMemorySize, 64*256*4);
    cudaFuncSetAttribute(k_lstm,   cudaFuncAttributeMaxDynamicSharedMemorySize, LSTM_SMEM);
    cudaFuncSetAttribute(k_emit,   cudaFuncAttributeMaxDynamicSharedMemorySize, (64*520 + 12*516)*4);

    dim3 gA(L_, 8);
    k_ingate<<<gA, 256, 64*256*4>>>(sent, emb, Wihf, bf, Wihb, bb);
    k_lstm<<<32, 256, LSTM_SMEM>>>(Whhf, Whhb);
    k_emit<<<L_, 768, (64*520 + 12*516)*4>>>(Wem, bem);
    k_crf<<<B_, 32>>>(tags, trans);
    k_mean<<<1, 32>>>(out);
}

// round 10
// speedup vs baseline: 1.2846x; 1.2846x over previous
#include <cuda_runtime.h>
#include <cuda_bf16.h>
#include <math.h>
#include <cstdint>

#define L_ 512
#define B_ 64
#define E_ 256
#define H_ 256
#define T_ 12
#define CS 8    // cluster size (verified working)

typedef unsigned long long u64;

// ---------------- helpers ----------------
__device__ __forceinline__ u64 fma2(u64 a, u64 b, u64 c) {
    u64 d;
    asm("fma.rn.f32x2 %0, %1, %2, %3;" : "=l"(d) : "l"(a), "l"(b), "l"(c));
    return d;
}
__device__ __forceinline__ float2 unpack2(u64 v) {
    float2 r;
    asm("mov.b64 {%0, %1}, %2;" : "=f"(r.x), "=f"(r.y) : "l"(v));
    return r;
}
__device__ __forceinline__ float tanhap(float x) {
    float y;
    asm("tanh.approx.f32 %0, %1;" : "=f"(y) : "f"(x));
    return y;
}
__device__ __forceinline__ float sigap(float x) {
    return fmaf(0.5f, tanhap(0.5f * x), 0.5f);
}
__device__ __forceinline__ float ex2f(float x) {
    float y;
    asm("ex2.approx.f32 %0, %1;" : "=f"(y) : "f"(x));
    return y;
}
__device__ __forceinline__ float lg2f(float x) {
    float y;
    asm("lg2.approx.f32 %0, %1;" : "=f"(y) : "f"(x));
    return y;
}
__device__ __forceinline__ uint32_t smem_u32(const void* p) {
    uint32_t a;
    asm("{ .reg .u64 t; cvta.to.shared.u64 t, %1; cvt.u32.u64 %0, t; }" : "=r"(a) : "l"(p));
    return a;
}
__device__ __forceinline__ uint32_t packbf(float lo, float hi) {
    uint32_t r;
    asm("cvt.rn.bf16x2.f32 %0, %1, %2;" : "=r"(r) : "f"(hi), "f"(lo));
    return r;
}
__device__ __forceinline__ void ldsm_x4(uint32_t& r0, uint32_t& r1, uint32_t& r2, uint32_t& r3, uint32_t addr) {
    asm volatile("ldmatrix.sync.aligned.m8n8.x4.shared.b16 {%0,%1,%2,%3}, [%4];"
        : "=r"(r0), "=r"(r1), "=r"(r2), "=r"(r3) : "r"(addr));
}
__device__ __forceinline__ void mma16816(float& d0, float& d1, float& d2, float& d3,
                                         uint32_t a0, uint32_t a1, uint32_t a2, uint32_t a3,
                                         uint32_t b0, uint32_t b1) {
    asm volatile("mma.sync.aligned.m16n8k16.row.col.f32.bf16.bf16.f32 "
        "{%0,%1,%2,%3}, {%4,%5,%6,%7}, {%8,%9}, {%0,%1,%2,%3};"
        : "+f"(d0), "+f"(d1), "+f"(d2), "+f"(d3)
        : "r"(a0), "r"(a1), "r"(a2), "r"(a3), "r"(b0), "r"(b1));
}
__device__ __forceinline__ uint32_t mapa_rank(uint32_t local, uint32_t rank) {
    uint32_t r;
    asm("mapa.shared::cluster.u32 %0, %1, %2;" : "=r"(r) : "r"(local), "r"(rank));
    return r;
}
__device__ __forceinline__ void mbar_arrive_remote(uint32_t remAddr) {
    asm volatile("mbarrier.arrive.release.cluster.shared::cluster.b64 _, [%0];"
                 :: "r"(remAddr) : "memory");
}
__device__ __forceinline__ void mbar_wait_cluster(uint32_t mbar, uint32_t parity) {
    uint32_t done = 0;
    while (!done) {
        asm volatile(
            "{\n\t.reg .pred p;\n\t"
            "mbarrier.try_wait.parity.acquire.cluster.shared::cta.b64 p, [%1], %2, 0x989680;\n\t"
            "selp.b32 %0, 1, 0, p;\n\t}"
            : "=r"(done) : "r"(mbar), "r"(parity) : "memory");
    }
}

// ---------------- scratch ----------------
__device__ float g_gx[(size_t)2*L_*1024*B_];          // input gates TRANSPOSED: [2][L][gate-row j][b]
__device__ __nv_bfloat16 g_hb[(size_t)2*L_*B_*H_];    // hidden bf16
__device__ float g_emit[(size_t)L_*B_*T_];
__device__ float g_nll[B_];

// ---------------- input-gate GEMM (f32x2 packed; transposed store; R8-identical) ----------------
__global__ __launch_bounds__(256, 1) void k_ingate(
    const int* __restrict__ sent, const float* __restrict__ emb,
    const float* __restrict__ Wf, const float* __restrict__ bfv,
    const float* __restrict__ Wb, const float* __restrict__ bbv)
{
    extern __shared__ float Xs[];
    __shared__ int tok[B_];
    int l   = blockIdx.x;
    int tid = threadIdx.x;
    if (tid < B_) tok[tid] = sent[tid*L_ + l];
    __syncthreads();
    float4* Xs4 = (float4*)Xs;
    #pragma unroll
    for (int i = 0; i < 16; i++) {
        int e = i*256 + tid;
        int r = e >> 6, kq = e & 63;
        Xs4[e] = ((const float4*)emb)[(size_t)tok[r]*64 + kq];
    }
    __syncthreads();

    int j   = blockIdx.y*256 + tid;
    int dir = j >> 10, jj = j & 1023;
    const float* W = dir ? Wb : Wf;
    const ulonglong2* W2 = (const ulonglong2*)(W + (size_t)jj*256);
    const ulonglong2* X2 = (const ulonglong2*)Xs;

    u64 acc2[64];
    #pragma unroll
    for (int r = 0; r < 64; r++) acc2[r] = 0ull;

    #pragma unroll 1
    for (int k4 = 0; k4 < 64; k4++) {
        ulonglong2 w = W2[k4];
        #pragma unroll
        for (int r = 0; r < 64; r++) {
            ulonglong2 x = X2[r*64 + k4];
            acc2[r] = fma2(w.x, x.x, acc2[r]);
            acc2[r] = fma2(w.y, x.y, acc2[r]);
        }
    }
    float bias = (dir ? bbv : bfv)[jj];
    float* outp = g_gx + ((size_t)(dir*L_ + l)*1024 + jj)*64;
    #pragma unroll
    for (int r4 = 0; r4 < 16; r4++) {
        float2 pa = unpack2(acc2[4*r4+0]);
        float2 pb = unpack2(acc2[4*r4+1]);
        float2 pc = unpack2(acc2[4*r4+2]);
        float2 pd = unpack2(acc2[4*r4+3]);
        *(float4*)(outp + 4*r4) = make_float4(pa.x+pa.y+bias, pb.x+pb.y+bias,
                                              pc.x+pc.y+bias, pd.x+pd.y+bias);
    }
}

// ---------------- persistent LSTM: mma.sync, L2 h-exchange (R8 skeleton), gx fused into acc ----------------
// 32 CTAs = (dir 2) x (batch-half 2) x (rank 8). CTA owns hids [32p,32p+32), batches [32bh,32bh+32).
static const int BS_PITCH_B = 528;                    // bytes per B-tile row (32 rows)
static const int SM_PS      = 32 * BS_PITCH_B;        // 16896 (B tile)
static const int PS_PITCH   = 34;
static const int SM_MBAR    = SM_PS + 128*PS_PITCH*4; // 16896 + 17408 = 34304
static const int LSTM_SMEM  = SM_MBAR + 128;

__global__ __launch_bounds__(256, 1) __cluster_dims__(CS, 1, 1)
void k_lstm(const float* __restrict__ Whf, const float* __restrict__ Whb)
{
    extern __shared__ __align__(1024) char sm[];
    float* Ps = (float*)(sm + SM_PS);
    uint32_t smb = smem_u32(sm);
    int d  = blockIdx.x >> 4;             // direction
    int bh = (blockIdx.x >> 3) & 1;       // batch half
    uint32_t p;
    asm("mov.u32 %0, %%cluster_ctarank;" : "=r"(p));
    int hb = (int)p * 32;
    int tid = threadIdx.x;
    int w = tid >> 5, l = tid & 31;
    const float* W = d ? Whb : Whf;

    if (tid == 0) {
        asm volatile("mbarrier.init.shared.b64 [%0], %1;" :: "r"(smb + SM_MBAR),     "r"((uint32_t)CS) : "memory");
        asm volatile("mbarrier.init.shared.b64 [%0], %1;" :: "r"(smb + SM_MBAR + 8), "r"((uint32_t)CS) : "memory");
    }
    __syncthreads();
    asm volatile("barrier.cluster.arrive.aligned;" ::: "memory");
    asm volatile("barrier.cluster.wait.aligned;" ::: "memory");

    // ---- A fragments: warp w -> m-rows [16w,16w+16), all 32 n ----
    int r0 = 16*w + (l >> 2), r1 = r0 + 8;
    const float* wr0 = W + (size_t)((r0 >> 5)*H_ + hb + (r0 & 31))*H_;
    const float* wr1 = W + (size_t)((r1 >> 5)*H_ + hb + (r1 & 31))*H_;
    uint32_t A0[16], A1[16], A2[16], A3[16];
    {
        int kc0 = (l & 3)*2;
        #pragma unroll
        for (int kt = 0; kt < 16; kt++) {
            int kc = kt*16 + kc0;
            A0[kt] = packbf(wr0[kc],   wr0[kc+1]);
            A1[kt] = packbf(wr1[kc],   wr1[kc+1]);
            A2[kt] = packbf(wr0[kc+8], wr0[kc+9]);
            A3[kt] = packbf(wr1[kc+8], wr1[kc+9]);
        }
    }

    // ldmatrix per-lane row base addresses (4 n-tiles of 8 local batches)
    uint32_t rowa[4];
    {
        int lrow = l & 7, grp = l >> 3;
        #pragma unroll
        for (int nt = 0; nt < 4; nt++)
            rowa[nt] = smb + (uint32_t)((nt*8 + lrow)*BS_PITCH_B + grp*16);
    }

    // gx accumulator-layout mapping: this thread's gate-rows r0,r1 -> global gx rows
    int jg0 = (r0 >> 5)*256 + hb + (r0 & 31);
    int jg1 = (r1 >> 5)*256 + hb + (r1 & 31);
    int cc  = (l & 3)*2;

    // phase-B mapping: thread owns (hid hl 0..31, local batches 4q..4q+3)
    int hl = tid & 31, q = tid >> 5;
    float cst[4];
    #pragma unroll
    for (int k = 0; k < 4; k++) cst[k] = 0.f;

    uint32_t rem0 = 0, rem1 = 0;
    if (tid < CS) {
        rem0 = mapa_rank(smb + SM_MBAR,     (uint32_t)tid);
        rem1 = mapa_rank(smb + SM_MBAR + 8, (uint32_t)tid);
    }

    for (int s = 0; s < L_; s++) {
        int t = d ? (L_-1-s) : s;

        // ---- gx prefetch in accumulator layout (independent of h) ----
        float2 gx0[4], gx1[4];
        {
            const float* base = g_gx + ((size_t)(d*L_ + t)*1024)*64 + 32*bh + cc;
            #pragma unroll
            for (int nt = 0; nt < 4; nt++) {
                gx0[nt] = *(const float2*)(base + (size_t)jg0*64 + nt*8);
                gx1[nt] = *(const float2*)(base + (size_t)jg1*64 + nt*8);
            }
        }

        // ---- wait + stage h (bf16 copy, this batch half only: 16 KB) ----
        if (s == 0) {
            for (int i = tid; i < SM_PS/4; i += 256) ((uint32_t*)sm)[i] = 0;
        } else {
            int sp = s - 1;
            mbar_wait_cluster(smb + SM_MBAR + (sp & 1)*8, (uint32_t)((sp >> 1) & 1));
            int tprev = d ? (t+1) : (t-1);
            const uint4* hsrc = (const uint4*)(g_hb + (((size_t)d*L_ + tprev)*B_ + 32*bh)*H_);
            #pragma unroll
            for (int i = 0; i < 4; i++) {
                int idx = i*256 + tid;
                int b = idx >> 5, kq = idx & 31;
                *(uint4*)(sm + b*BS_PITCH_B + kq*16) = hsrc[idx];
            }
        }
        __syncthreads();

        // ---- MMA mainloop: D[128,32], warp covers 16 m x 32 n ----
        float acc[4][4];
        #pragma unroll
        for (int nt = 0; nt < 4; nt++)
            #pragma unroll
            for (int k = 0; k < 4; k++) acc[nt][k] = 0.f;

        #pragma unroll
        for (int ktp = 0; ktp < 8; ktp++) {
            #pragma unroll
            for (int nt = 0; nt < 4; nt++) {
                uint32_t b0, b1, b2, b3;
                ldsm_x4(b0, b1, b2, b3, rowa[nt] + ktp*64);
                mma16816(acc[nt][0], acc[nt][1], acc[nt][2], acc[nt][3],
                         A0[2*ktp], A1[2*ktp], A2[2*ktp], A3[2*ktp], b0, b1);
                mma16816(acc[nt][0], acc[nt][1], acc[nt][2], acc[nt][3],
                         A0[2*ktp+1], A1[2*ktp+1], A2[2*ktp+1], A3[2*ktp+1], b2, b3);
            }
        }

        // ---- Ps = D + gx (single store; no prefill, no RMW) ----
        {
            #pragma unroll
            for (int nt = 0; nt < 4; nt++) {
                *(float2*)(Ps + r0*PS_PITCH + nt*8 + cc) =
                    make_float2(acc[nt][0] + gx0[nt].x, acc[nt][1] + gx0[nt].y);
                *(float2*)(Ps + r1*PS_PITCH + nt*8 + cc) =
                    make_float2(acc[nt][2] + gx1[nt].x, acc[nt][3] + gx1[nt].y);
            }
        }
        __syncthreads();

        // ---- phase B: activations, c update, h out (bf16) ----
        float hout[4];
        #pragma unroll
        for (int j = 0; j < 2; j++) {
            float2 vi = *(const float2*)(Ps + (  0 + hl)*PS_PITCH + q*4 + 2*j);
            float2 vf = *(const float2*)(Ps + ( 32 + hl)*PS_PITCH + q*4 + 2*j);
            float2 vg = *(const float2*)(Ps + ( 64 + hl)*PS_PITCH + q*4 + 2*j);
            float2 vo = *(const float2*)(Ps + ( 96 + hl)*PS_PITCH + q*4 + 2*j);
            {
                float ig = sigap(vi.x), fg = sigap(vf.x), gg = tanhap(vg.x), og = sigap(vo.x);
                cst[2*j] = fg*cst[2*j] + ig*gg;
                hout[2*j] = og * tanhap(cst[2*j]);
            }
            {
                float ig = sigap(vi.y), fg = sigap(vf.y), gg = tanhap(vg.y), og = sigap(vo.y);
                cst[2*j+1] = fg*cst[2*j+1] + ig*gg;
                hout[2*j+1] = og * tanhap(cst[2*j+1]);
            }
        }
        {
            __nv_bfloat16* hbd = g_hb + (((size_t)d*L_ + t)*B_ + 32*bh + q*4)*H_ + hb + hl;
            #pragma unroll
            for (int k = 0; k < 4; k++) hbd[(size_t)k*H_] = __float2bfloat16(hout[k]);
        }
        __syncthreads();
        if (tid < CS && s < L_-1) {
            mbar_arrive_remote((s & 1) ? rem1 : rem0);
        }
    }
}

// ---------------- emission GEMM (reads bf16 h; R8-identical) ----------------
__global__ __launch_bounds__(768) void k_emit(const float* __restrict__ Wem,
                                              const float* __restrict__ bem)
{
    extern __shared__ float smc[];
    float* Hcat = smc;            // [64][520]
    float* Wsm  = smc + 64*520;   // [12][516]
    int l   = blockIdx.x;
    int tid = threadIdx.x;
    const uint4* hf  = (const uint4*)(g_hb + ((size_t)0*L_ + l)*B_*H_);
    const uint4* hbk = (const uint4*)(g_hb + ((size_t)1*L_ + l)*B_*H_);
    for (int e = tid; e < 2048; e += 768) {
        int r = e >> 5, kq = e & 31;
        uint4 vf = hf[e], vb = hbk[e];
        const __nv_bfloat162* pf = (const __nv_bfloat162*)&vf;
        const __nv_bfloat162* pb = (const __nv_bfloat162*)&vb;
        float* df = Hcat + r*520 + kq*8;
        float* db = Hcat + r*520 + 256 + kq*8;
        #pragma unroll
        for (int qq = 0; qq < 4; qq++) {
            float2 f2 = __bfloat1622float2(pf[qq]);
            float2 b2 = __bfloat1622float2(pb[qq]);
            df[2*qq] = f2.x; df[2*qq+1] = f2.y;
            db[2*qq] = b2.x; db[2*qq+1] = b2.y;
        }
    }
    for (int e = tid; e < 12*512; e += 768)
        Wsm[(e >> 9)*516 + (e & 511)] = Wem[e];
    __syncthreads();

    int b = tid / 12, tg = tid - b*12;
    float acc = bem[tg];
    const float4* hrow = (const float4*)(Hcat + b*520);
    const float4* wrow = (const float4*)(Wsm + tg*516);
    #pragma unroll 8
    for (int k4 = 0; k4 < 128; k4++) {
        float4 x = hrow[k4]; float4 w = wrow[k4];
        acc += w.x*x.x + w.y*x.y + w.z*x.z + w.w*x.w;
    }
    g_emit[((size_t)l*B_ + b)*T_ + tg] = acc;
}

// ---------------- CRF NLL: emissions staged in smem, base-2 scan ----------------
__global__ void k_crf(const int* __restrict__ tags, const float* __restrict__ trans)
{
    __shared__ float se[512*12];    // this batch's emissions, 24 KB
    __shared__ float tr[T_*T_];
    int b = blockIdx.x;
    int lane = threadIdx.x;
    for (int i = lane; i < T_*T_; i += 32) tr[i] = trans[i];
    // stage emissions: float4 bursts; se[l*12 + t], f4 index l*3 + j
    {
        const float4* src = (const float4*)g_emit;
        float4* dst = (float4*)se;
        for (int i = lane; i < 1536; i += 32) {
            int l = i / 3, j = i - 3*l;
            dst[i] = src[((size_t)l*64 + b)*3 + j];
        }
    }
    __syncwarp();

    const unsigned FULL = 0xffffffffu;
    const float I2 = 1.4426950408889634f;
    const float LN2 = 0.6931471805599453f;
    int mylane = (lane < T_) ? lane : 0;
    float trr2[T_];
    #pragma unroll
    for (int t2 = 0; t2 < T_; t2++) trr2[t2] = tr[t2*T_ + mylane] * I2;

    float a2 = se[mylane] * I2;
    #pragma unroll 4
    for (int l = 1; l < L_; l++) {
        float e2 = se[l*12 + mylane] * I2;
        float v[T_];
        #pragma unroll
        for (int t2 = 0; t2 < T_; t2++)
            v[t2] = __shfl_sync(FULL, a2, t2) + trr2[t2];
        float ex[T_];
        ex[0] = 1.0f;
        #pragma unroll
        for (int t2 = 1; t2 < T_; t2++) ex[t2] = ex2f(v[t2] - v[0]);
        float s01 = ex[0] + ex[1],  s23 = ex[2] + ex[3];
        float s45 = ex[4] + ex[5],  s67 = ex[6] + ex[7];
        float s89 = ex[8] + ex[9],  sAB = ex[10] + ex[11];
        float ssum = ((s01 + s23) + (s45 + s67)) + (s89 + sAB);
        a2 = v[0] + lg2f(ssum) + e2;
    }
    float am = (lane < T_) ? a2 : -1e30f;
    float mm = am;
    for (int o = 16; o; o >>= 1) mm = fmaxf(mm, __shfl_xor_sync(FULL, mm, o));
    float es = (lane < T_) ? ex2f(a2 - mm) : 0.f;
    for (int o = 16; o; o >>= 1) es += __shfl_xor_sync(FULL, es, o);
    float logZ = (mm + lg2f(es)) * LN2;

    float eg = 0.f, tg2 = 0.f;
    for (int l = lane; l < L_; l += 32) {
        int tv = tags[b*L_ + l];
        eg += se[l*12 + tv];
    }
    for (int l = lane; l < L_-1; l += 32) {
        int t0v = tags[b*L_ + l], t1v = tags[b*L_ + l + 1];
        tg2 += tr[t0v*T_ + t1v];
    }
    for (int o = 16; o; o >>= 1) {
        eg  += __shfl_xor_sync(FULL, eg,  o);
        tg2 += __shfl_xor_sync(FULL, tg2, o);
    }
    if (lane == 0) g_nll[b] = logZ - eg - tg2;
}

__global__ void k_mean(float* out)
{
    int lane = threadIdx.x;
    float s = (lane < 32) ? g_nll[lane] + g_nll[lane + 32] : 0.f;
    s += __shfl_xor_sync(0xffffffffu, s, 16);
    s += __shfl_xor_sync(0xffffffffu, s, 8);
    s += __shfl_xor_sync(0xffffffffu, s, 4);
    s += __shfl_xor_sync(0xffffffffu, s, 2);
    s += __shfl_xor_sync(0xffffffffu, s, 1);
    if (lane == 0) out[0] = s / (float)B_;
}

// ---------------- launch ----------------
extern "C" void kernel_launch(void* const* d_in, const int* in_sizes, int n_in,
                              void* d_out, int out_size)
{
    const int*   sent  = (const int*)  d_in[0];
    const int*   tags  = (const int*)  d_in[1];
    const float* emb   = (const float*)d_in[2];
    const float* Wihf  = (const float*)d_in[3];
    const float* Whhf  = (const float*)d_in[4];
    const float* bf    = (const float*)d_in[5];
    const float* Wihb  = (const float*)d_in[6];
    const float* Whhb  = (const float*)d_in[7];
    const float* bb    = (const float*)d_in[8];
    const float* Wem   = (const float*)d_in[9];
    const float* bem   = (const float*)d_in[10];
    const float* trans = (const float*)d_in[11];
    float* out = (float*)d_out;

    cudaFuncSetAttribute(k_ingate, cudaFuncAttributeMaxDynamicSharedMemorySize, 64*256*4);
    cudaFuncSetAttribute(k_lstm,   cudaFuncAttributeMaxDynamicSharedMemorySize, LSTM_SMEM);
    cudaFuncSetAttribute(k_emit,   cudaFuncAttributeMaxDynamicSharedMemorySize, (64*520 + 12*516)*4);

    dim3 gA(L_, 8);
    k_ingate<<<gA, 256, 64*256*4>>>(sent, emb, Wihf, bf, Wihb, bb);
    k_lstm<<<32, 256, LSTM_SMEM>>>(Whhf, Whhb);
    k_emit<<<L_, 768, (64*520 + 12*516)*4>>>(Wem, bem);
    k_crf<<<B_, 32>>>(tags, trans);
    k_mean<<<1, 32>>>(out);
}

// round 11
// speedup vs baseline: 1.4819x; 1.1536x over previous
#include <cuda_runtime.h>
#include <cuda_bf16.h>
#include <math.h>
#include <cstdint>

#define L_ 512
#define B_ 64
#define E_ 256
#define H_ 256
#define T_ 12
#define CS 8    // cluster size (verified working)

typedef unsigned long long u64;

// ---------------- helpers ----------------
__device__ __forceinline__ u64 fma2(u64 a, u64 b, u64 c) {
    u64 d;
    asm("fma.rn.f32x2 %0, %1, %2, %3;" : "=l"(d) : "l"(a), "l"(b), "l"(c));
    return d;
}
__device__ __forceinline__ float2 unpack2(u64 v) {
    float2 r;
    asm("mov.b64 {%0, %1}, %2;" : "=f"(r.x), "=f"(r.y) : "l"(v));
    return r;
}
__device__ __forceinline__ float tanhap(float x) {
    float y;
    asm("tanh.approx.f32 %0, %1;" : "=f"(y) : "f"(x));
    return y;
}
__device__ __forceinline__ float sigap(float x) {
    return fmaf(0.5f, tanhap(0.5f * x), 0.5f);
}
__device__ __forceinline__ float ex2f(float x) {
    float y;
    asm("ex2.approx.f32 %0, %1;" : "=f"(y) : "f"(x));
    return y;
}
__device__ __forceinline__ float lg2f(float x) {
    float y;
    asm("lg2.approx.f32 %0, %1;" : "=f"(y) : "f"(x));
    return y;
}
__device__ __forceinline__ uint32_t smem_u32(const void* p) {
    uint32_t a;
    asm("{ .reg .u64 t; cvta.to.shared.u64 t, %1; cvt.u32.u64 %0, t; }" : "=r"(a) : "l"(p));
    return a;
}
__device__ __forceinline__ uint32_t packbf(float lo, float hi) {
    uint32_t r;
    asm("cvt.rn.bf16x2.f32 %0, %1, %2;" : "=r"(r) : "f"(hi), "f"(lo));
    return r;
}
__device__ __forceinline__ void ldsm_x4(uint32_t& r0, uint32_t& r1, uint32_t& r2, uint32_t& r3, uint32_t addr) {
    asm volatile("ldmatrix.sync.aligned.m8n8.x4.shared.b16 {%0,%1,%2,%3}, [%4];"
        : "=r"(r0), "=r"(r1), "=r"(r2), "=r"(r3) : "r"(addr));
}
__device__ __forceinline__ void mma16816(float& d0, float& d1, float& d2, float& d3,
                                         uint32_t a0, uint32_t a1, uint32_t a2, uint32_t a3,
                                         uint32_t b0, uint32_t b1) {
    asm volatile("mma.sync.aligned.m16n8k16.row.col.f32.bf16.bf16.f32 "
        "{%0,%1,%2,%3}, {%4,%5,%6,%7}, {%8,%9}, {%0,%1,%2,%3};"
        : "+f"(d0), "+f"(d1), "+f"(d2), "+f"(d3)
        : "r"(a0), "r"(a1), "r"(a2), "r"(a3), "r"(b0), "r"(b1));
}
__device__ __forceinline__ uint32_t mapa_rank(uint32_t local, uint32_t rank) {
    uint32_t r;
    asm("mapa.shared::cluster.u32 %0, %1, %2;" : "=r"(r) : "r"(local), "r"(rank));
    return r;
}
__device__ __forceinline__ void mbar_arrive_remote(uint32_t remAddr) {
    asm volatile("mbarrier.arrive.release.cluster.shared::cluster.b64 _, [%0];"
                 :: "r"(remAddr) : "memory");
}
__device__ __forceinline__ void mbar_wait_cluster(uint32_t mbar, uint32_t parity) {
    uint32_t done = 0;
    while (!done) {
        asm volatile(
            "{\n\t.reg .pred p;\n\t"
            "mbarrier.try_wait.parity.acquire.cluster.shared::cta.b64 p, [%1], %2, 0x989680;\n\t"
            "selp.b32 %0, 1, 0, p;\n\t}"
            : "=r"(done) : "r"(mbar), "r"(parity) : "memory");
    }
}

// ---------------- scratch ----------------
__device__ float g_gx[(size_t)2*L_*1024*B_];          // input gates TRANSPOSED: [2][L][gate-row j][b]
__device__ __nv_bfloat16 g_hb[(size_t)2*L_*B_*H_];    // hidden bf16
__device__ float g_emit[(size_t)L_*B_*T_];
__device__ float g_nll[B_];

// ---------------- input-gate GEMM (f32x2 packed; transposed store; unchanged) ----------------
__global__ __launch_bounds__(256, 1) void k_ingate(
    const int* __restrict__ sent, const float* __restrict__ emb,
    const float* __restrict__ Wf, const float* __restrict__ bfv,
    const float* __restrict__ Wb, const float* __restrict__ bbv)
{
    extern __shared__ float Xs[];
    __shared__ int tok[B_];
    int l   = blockIdx.x;
    int tid = threadIdx.x;
    if (tid < B_) tok[tid] = sent[tid*L_ + l];
    __syncthreads();
    float4* Xs4 = (float4*)Xs;
    #pragma unroll
    for (int i = 0; i < 16; i++) {
        int e = i*256 + tid;
        int r = e >> 6, kq = e & 63;
        Xs4[e] = ((const float4*)emb)[(size_t)tok[r]*64 + kq];
    }
    __syncthreads();

    int j   = blockIdx.y*256 + tid;
    int dir = j >> 10, jj = j & 1023;
    const float* W = dir ? Wb : Wf;
    const ulonglong2* W2 = (const ulonglong2*)(W + (size_t)jj*256);
    const ulonglong2* X2 = (const ulonglong2*)Xs;

    u64 acc2[64];
    #pragma unroll
    for (int r = 0; r < 64; r++) acc2[r] = 0ull;

    #pragma unroll 1
    for (int k4 = 0; k4 < 64; k4++) {
        ulonglong2 w = W2[k4];
        #pragma unroll
        for (int r = 0; r < 64; r++) {
            ulonglong2 x = X2[r*64 + k4];
            acc2[r] = fma2(w.x, x.x, acc2[r]);
            acc2[r] = fma2(w.y, x.y, acc2[r]);
        }
    }
    float bias = (dir ? bbv : bfv)[jj];
    float* outp = g_gx + ((size_t)(dir*L_ + l)*1024 + jj)*64;
    #pragma unroll
    for (int r4 = 0; r4 < 16; r4++) {
        float2 pa = unpack2(acc2[4*r4+0]);
        float2 pb = unpack2(acc2[4*r4+1]);
        float2 pc = unpack2(acc2[4*r4+2]);
        float2 pd = unpack2(acc2[4*r4+3]);
        *(float4*)(outp + 4*r4) = make_float4(pa.x+pa.y+bias, pb.x+pb.y+bias,
                                              pc.x+pc.y+bias, pd.x+pd.y+bias);
    }
}

// ---------------- persistent LSTM: mma.sync, L2 h-exchange, batch-QUARTER split ----------------
// 64 CTAs = (dir 2) x (batch-quarter 4) x (rank 8). CTA owns hids [32p,32p+32), batches [16bq,16bq+16).
// D[128 gate-rows, 16 batch] = W_local[128,256] x h_q[16,256]^T
static const int BS_PITCH_B = 528;                    // bytes per B-tile row (16 rows)
static const int SM_PS      = 16 * BS_PITCH_B;        // 8448 (B tile)
static const int PS_PITCH   = 18;                     // floats per Ps row (16 batch + pad)
static const int SM_MBAR    = SM_PS + 128*PS_PITCH*4; // 8448 + 9216 = 17664
static const int LSTM_SMEM  = SM_MBAR + 128;

__global__ __launch_bounds__(256, 1) __cluster_dims__(CS, 1, 1)
void k_lstm(const float* __restrict__ Whf, const float* __restrict__ Whb)
{
    extern __shared__ __align__(1024) char sm[];
    float* Ps = (float*)(sm + SM_PS);
    uint32_t smb = smem_u32(sm);
    int d  = blockIdx.x >> 5;             // direction
    int bq = (blockIdx.x >> 3) & 3;       // batch quarter
    uint32_t p;
    asm("mov.u32 %0, %%cluster_ctarank;" : "=r"(p));
    int hb = (int)p * 32;
    int tid = threadIdx.x;
    int w = tid >> 5, l = tid & 31;
    const float* W = d ? Whb : Whf;

    if (tid == 0) {
        asm volatile("mbarrier.init.shared.b64 [%0], %1;" :: "r"(smb + SM_MBAR),     "r"((uint32_t)CS) : "memory");
        asm volatile("mbarrier.init.shared.b64 [%0], %1;" :: "r"(smb + SM_MBAR + 8), "r"((uint32_t)CS) : "memory");
    }
    __syncthreads();
    asm volatile("barrier.cluster.arrive.aligned;" ::: "memory");
    asm volatile("barrier.cluster.wait.aligned;" ::: "memory");

    // ---- A fragments: warp w -> m-rows [16w,16w+16), all 16 n ----
    int r0 = 16*w + (l >> 2), r1 = r0 + 8;
    const float* wr0 = W + (size_t)((r0 >> 5)*H_ + hb + (r0 & 31))*H_;
    const float* wr1 = W + (size_t)((r1 >> 5)*H_ + hb + (r1 & 31))*H_;
    uint32_t A0[16], A1[16], A2[16], A3[16];
    {
        int kc0 = (l & 3)*2;
        #pragma unroll
        for (int kt = 0; kt < 16; kt++) {
            int kc = kt*16 + kc0;
            A0[kt] = packbf(wr0[kc],   wr0[kc+1]);
            A1[kt] = packbf(wr1[kc],   wr1[kc+1]);
            A2[kt] = packbf(wr0[kc+8], wr0[kc+9]);
            A3[kt] = packbf(wr1[kc+8], wr1[kc+9]);
        }
    }

    // ldmatrix per-lane row base addresses (2 n-tiles of 8 local batches)
    uint32_t rowa[2];
    {
        int lrow = l & 7, grp = l >> 3;
        #pragma unroll
        for (int nt = 0; nt < 2; nt++)
            rowa[nt] = smb + (uint32_t)((nt*8 + lrow)*BS_PITCH_B + grp*16);
    }

    // gx accumulator-layout mapping
    int jg0 = (r0 >> 5)*256 + hb + (r0 & 31);
    int jg1 = (r1 >> 5)*256 + hb + (r1 & 31);
    int cc  = (l & 3)*2;

    // phase-B mapping: thread owns (hid hl 0..31, local batches 2q..2q+1), q = tid>>5
    int hl = tid & 31, q = tid >> 5;
    float cst[2];
    cst[0] = 0.f; cst[1] = 0.f;

    uint32_t rem0 = 0, rem1 = 0;
    if (tid < CS) {
        rem0 = mapa_rank(smb + SM_MBAR,     (uint32_t)tid);
        rem1 = mapa_rank(smb + SM_MBAR + 8, (uint32_t)tid);
    }

    for (int s = 0; s < L_; s++) {
        int t = d ? (L_-1-s) : s;

        // ---- gx prefetch in accumulator layout (independent of h) ----
        float2 gx0[2], gx1[2];
        {
            const float* base = g_gx + ((size_t)(d*L_ + t)*1024)*64 + 16*bq + cc;
            #pragma unroll
            for (int nt = 0; nt < 2; nt++) {
                gx0[nt] = *(const float2*)(base + (size_t)jg0*64 + nt*8);
                gx1[nt] = *(const float2*)(base + (size_t)jg1*64 + nt*8);
            }
        }

        // ---- wait + stage h (bf16 copy, this batch quarter: 8 KB) ----
        if (s == 0) {
            for (int i = tid; i < SM_PS/4; i += 256) ((uint32_t*)sm)[i] = 0;
        } else {
            int sp = s - 1;
            mbar_wait_cluster(smb + SM_MBAR + (sp & 1)*8, (uint32_t)((sp >> 1) & 1));
            int tprev = d ? (t+1) : (t-1);
            const uint4* hsrc = (const uint4*)(g_hb + (((size_t)d*L_ + tprev)*B_ + 16*bq)*H_);
            #pragma unroll
            for (int i = 0; i < 2; i++) {
                int idx = i*256 + tid;          // 512 uint4 total
                int b = idx >> 5, kq = idx & 31;
                *(uint4*)(sm + b*BS_PITCH_B + kq*16) = hsrc[idx];
            }
        }
        __syncthreads();

        // ---- MMA mainloop: D[128,16], warp covers 16 m x 16 n ----
        float acc[2][4];
        #pragma unroll
        for (int nt = 0; nt < 2; nt++)
            #pragma unroll
            for (int k = 0; k < 4; k++) acc[nt][k] = 0.f;

        #pragma unroll
        for (int ktp = 0; ktp < 8; ktp++) {
            #pragma unroll
            for (int nt = 0; nt < 2; nt++) {
                uint32_t b0, b1, b2, b3;
                ldsm_x4(b0, b1, b2, b3, rowa[nt] + ktp*64);
                mma16816(acc[nt][0], acc[nt][1], acc[nt][2], acc[nt][3],
                         A0[2*ktp], A1[2*ktp], A2[2*ktp], A3[2*ktp], b0, b1);
                mma16816(acc[nt][0], acc[nt][1], acc[nt][2], acc[nt][3],
                         A0[2*ktp+1], A1[2*ktp+1], A2[2*ktp+1], A3[2*ktp+1], b2, b3);
            }
        }

        // ---- Ps = D + gx (single store) ----
        {
            #pragma unroll
            for (int nt = 0; nt < 2; nt++) {
                *(float2*)(Ps + r0*PS_PITCH + nt*8 + cc) =
                    make_float2(acc[nt][0] + gx0[nt].x, acc[nt][1] + gx0[nt].y);
                *(float2*)(Ps + r1*PS_PITCH + nt*8 + cc) =
                    make_float2(acc[nt][2] + gx1[nt].x, acc[nt][3] + gx1[nt].y);
            }
        }
        __syncthreads();

        // ---- phase B: activations, c update, h out (bf16) ----
        float hout[2];
        {
            float2 vi = *(const float2*)(Ps + (  0 + hl)*PS_PITCH + q*2);
            float2 vf = *(const float2*)(Ps + ( 32 + hl)*PS_PITCH + q*2);
            float2 vg = *(const float2*)(Ps + ( 64 + hl)*PS_PITCH + q*2);
            float2 vo = *(const float2*)(Ps + ( 96 + hl)*PS_PITCH + q*2);
            {
                float ig = sigap(vi.x), fg = sigap(vf.x), gg = tanhap(vg.x), og = sigap(vo.x);
                cst[0] = fg*cst[0] + ig*gg;
                hout[0] = og * tanhap(cst[0]);
            }
            {
                float ig = sigap(vi.y), fg = sigap(vf.y), gg = tanhap(vg.y), og = sigap(vo.y);
                cst[1] = fg*cst[1] + ig*gg;
                hout[1] = og * tanhap(cst[1]);
            }
        }
        {
            __nv_bfloat16* hbd = g_hb + (((size_t)d*L_ + t)*B_ + 16*bq + q*2)*H_ + hb + hl;
            hbd[0]  = __float2bfloat16(hout[0]);
            hbd[H_] = __float2bfloat16(hout[1]);
        }
        __syncthreads();
        if (tid < CS && s < L_-1) {
            mbar_arrive_remote((s & 1) ? rem1 : rem0);
        }
    }
}

// ---------------- emission GEMM (reads bf16 h; unchanged) ----------------
__global__ __launch_bounds__(768) void k_emit(const float* __restrict__ Wem,
                                              const float* __restrict__ bem)
{
    extern __shared__ float smc[];
    float* Hcat = smc;            // [64][520]
    float* Wsm  = smc + 64*520;   // [12][516]
    int l   = blockIdx.x;
    int tid = threadIdx.x;
    const uint4* hf  = (const uint4*)(g_hb + ((size_t)0*L_ + l)*B_*H_);
    const uint4* hbk = (const uint4*)(g_hb + ((size_t)1*L_ + l)*B_*H_);
    for (int e = tid; e < 2048; e += 768) {
        int r = e >> 5, kq = e & 31;
        uint4 vf = hf[e], vb = hbk[e];
        const __nv_bfloat162* pf = (const __nv_bfloat162*)&vf;
        const __nv_bfloat162* pb = (const __nv_bfloat162*)&vb;
        float* df = Hcat + r*520 + kq*8;
        float* db = Hcat + r*520 + 256 + kq*8;
        #pragma unroll
        for (int qq = 0; qq < 4; qq++) {
            float2 f2 = __bfloat1622float2(pf[qq]);
            float2 b2 = __bfloat1622float2(pb[qq]);
            df[2*qq] = f2.x; df[2*qq+1] = f2.y;
            db[2*qq] = b2.x; db[2*qq+1] = b2.y;
        }
    }
    for (int e = tid; e < 12*512; e += 768)
        Wsm[(e >> 9)*516 + (e & 511)] = Wem[e];
    __syncthreads();

    int b = tid / 12, tg = tid - b*12;
    float acc = bem[tg];
    const float4* hrow = (const float4*)(Hcat + b*520);
    const float4* wrow = (const float4*)(Wsm + tg*516);
    #pragma unroll 8
    for (int k4 = 0; k4 < 128; k4++) {
        float4 x = hrow[k4]; float4 w = wrow[k4];
        acc += w.x*x.x + w.y*x.y + w.z*x.z + w.w*x.w;
    }
    g_emit[((size_t)l*B_ + b)*T_ + tg] = acc;
}

// ---------------- CRF NLL: emissions staged in smem, base-2 scan (unchanged) ----------------
__global__ void k_crf(const int* __restrict__ tags, const float* __restrict__ trans)
{
    __shared__ float se[512*12];
    __shared__ float tr[T_*T_];
    int b = blockIdx.x;
    int lane = threadIdx.x;
    for (int i = lane; i < T_*T_; i += 32) tr[i] = trans[i];
    {
        const float4* src = (const float4*)g_emit;
        float4* dst = (float4*)se;
        for (int i = lane; i < 1536; i += 32) {
            int l = i / 3, j = i - 3*l;
            dst[i] = src[((size_t)l*64 + b)*3 + j];
        }
    }
    __syncwarp();

    const unsigned FULL = 0xffffffffu;
    const float I2 = 1.4426950408889634f;
    const float LN2 = 0.6931471805599453f;
    int mylane = (lane < T_) ? lane : 0;
    float trr2[T_];
    #pragma unroll
    for (int t2 = 0; t2 < T_; t2++) trr2[t2] = tr[t2*T_ + mylane] * I2;

    float a2 = se[mylane] * I2;
    #pragma unroll 4
    for (int l = 1; l < L_; l++) {
        float e2 = se[l*12 + mylane] * I2;
        float v[T_];
        #pragma unroll
        for (int t2 = 0; t2 < T_; t2++)
            v[t2] = __shfl_sync(FULL, a2, t2) + trr2[t2];
        float ex[T_];
        ex[0] = 1.0f;
        #pragma unroll
        for (int t2 = 1; t2 < T_; t2++) ex[t2] = ex2f(v[t2] - v[0]);
        float s01 = ex[0] + ex[1],  s23 = ex[2] + ex[3];
        float s45 = ex[4] + ex[5],  s67 = ex[6] + ex[7];
        float s89 = ex[8] + ex[9],  sAB = ex[10] + ex[11];
        float ssum = ((s01 + s23) + (s45 + s67)) + (s89 + sAB);
        a2 = v[0] + lg2f(ssum) + e2;
    }
    float am = (lane < T_) ? a2 : -1e30f;
    float mm = am;
    for (int o = 16; o; o >>= 1) mm = fmaxf(mm, __shfl_xor_sync(FULL, mm, o));
    float es = (lane < T_) ? ex2f(a2 - mm) : 0.f;
    for (int o = 16; o; o >>= 1) es += __shfl_xor_sync(FULL, es, o);
    float logZ = (mm + lg2f(es)) * LN2;

    float eg = 0.f, tg2 = 0.f;
    for (int l = lane; l < L_; l += 32) {
        int tv = tags[b*L_ + l];
        eg += se[l*12 + tv];
    }
    for (int l = lane; l < L_-1; l += 32) {
        int t0v = tags[b*L_ + l], t1v = tags[b*L_ + l + 1];
        tg2 += tr[t0v*T_ + t1v];
    }
    for (int o = 16; o; o >>= 1) {
        eg  += __shfl_xor_sync(FULL, eg,  o);
        tg2 += __shfl_xor_sync(FULL, tg2, o);
    }
    if (lane == 0) g_nll[b] = logZ - eg - tg2;
}

__global__ void k_mean(float* out)
{
    int lane = threadIdx.x;
    float s = (lane < 32) ? g_nll[lane] + g_nll[lane + 32] : 0.f;
    s += __shfl_xor_sync(0xffffffffu, s, 16);
    s += __shfl_xor_sync(0xffffffffu, s, 8);
    s += __shfl_xor_sync(0xffffffffu, s, 4);
    s += __shfl_xor_sync(0xffffffffu, s, 2);
    s += __shfl_xor_sync(0xffffffffu, s, 1);
    if (lane == 0) out[0] = s / (float)B_;
}

// ---------------- launch ----------------
extern "C" void kernel_launch(void* const* d_in, const int* in_sizes, int n_in,
                              void* d_out, int out_size)
{
    const int*   sent  = (const int*)  d_in[0];
    const int*   tags  = (const int*)  d_in[1];
    const float* emb   = (const float*)d_in[2];
    const float* Wihf  = (const float*)d_in[3];
    const float* Whhf  = (const float*)d_in[4];
    const float* bf    = (const float*)d_in[5];
    const float* Wihb  = (const float*)d_in[6];
    const float* Whhb  = (const float*)d_in[7];
    const float* bb    = (const float*)d_in[8];
    const float* Wem   = (const float*)d_in[9];
    const float* bem   = (const float*)d_in[10];
    const float* trans = (const float*)d_in[11];
    float* out = (float*)d_out;

    cudaFuncSetAttribute(k_ingate, cudaFuncAttributeMaxDynamicSharedMemorySize, 64*256*4);
    cudaFuncSetAttribute(k_lstm,   cudaFuncAttributeMaxDynamicSharedMemorySize, LSTM_SMEM);
    cudaFuncSetAttribute(k_emit,   cudaFuncAttributeMaxDynamicSharedMemorySize, (64*520 + 12*516)*4);

    dim3 gA(L_, 8);
    k_ingate<<<gA, 256, 64*256*4>>>(sent, emb, Wihf, bf, Wihb, bb);
    k_lstm<<<64, 256, LSTM_SMEM>>>(Whhf, Whhb);
    k_emit<<<L_, 768, (64*520 + 12*516)*4>>>(Wem, bem);
    k_crf<<<B_, 32>>>(tags, trans);
    k_mean<<<1, 32>>>(out);
}

// round 12
// speedup vs baseline: 1.8617x; 1.2563x over previous
#include <cuda_runtime.h>
#include <cuda_bf16.h>
#include <math.h>
#include <cstdint>

#define L_ 512
#define B_ 64
#define E_ 256
#define H_ 256
#define T_ 12
#define CS 8    // cluster size (verified working)

typedef unsigned long long u64;

// ---------------- helpers ----------------
__device__ __forceinline__ float tanhap(float x) {
    float y;
    asm("tanh.approx.f32 %0, %1;" : "=f"(y) : "f"(x));
    return y;
}
__device__ __forceinline__ float sigap(float x) {
    return fmaf(0.5f, tanhap(0.5f * x), 0.5f);
}
__device__ __forceinline__ float ex2f(float x) {
    float y;
    asm("ex2.approx.f32 %0, %1;" : "=f"(y) : "f"(x));
    return y;
}
__device__ __forceinline__ float lg2f(float x) {
    float y;
    asm("lg2.approx.f32 %0, %1;" : "=f"(y) : "f"(x));
    return y;
}
__device__ __forceinline__ uint32_t smem_u32(const void* p) {
    uint32_t a;
    asm("{ .reg .u64 t; cvta.to.shared.u64 t, %1; cvt.u32.u64 %0, t; }" : "=r"(a) : "l"(p));
    return a;
}
__device__ __forceinline__ uint32_t packbf(float lo, float hi) {
    uint32_t r;
    asm("cvt.rn.bf16x2.f32 %0, %1, %2;" : "=r"(r) : "f"(hi), "f"(lo));
    return r;
}
__device__ __forceinline__ void ldsm_x4(uint32_t& r0, uint32_t& r1, uint32_t& r2, uint32_t& r3, uint32_t addr) {
    asm volatile("ldmatrix.sync.aligned.m8n8.x4.shared.b16 {%0,%1,%2,%3}, [%4];"
        : "=r"(r0), "=r"(r1), "=r"(r2), "=r"(r3) : "r"(addr));
}
__device__ __forceinline__ void mma16816(float& d0, float& d1, float& d2, float& d3,
                                         uint32_t a0, uint32_t a1, uint32_t a2, uint32_t a3,
                                         uint32_t b0, uint32_t b1) {
    asm volatile("mma.sync.aligned.m16n8k16.row.col.f32.bf16.bf16.f32 "
        "{%0,%1,%2,%3}, {%4,%5,%6,%7}, {%8,%9}, {%0,%1,%2,%3};"
        : "+f"(d0), "+f"(d1), "+f"(d2), "+f"(d3)
        : "r"(a0), "r"(a1), "r"(a2), "r"(a3), "r"(b0), "r"(b1));
}
__device__ __forceinline__ uint32_t mapa_rank(uint32_t local, uint32_t rank) {
    uint32_t r;
    asm("mapa.shared::cluster.u32 %0, %1, %2;" : "=r"(r) : "r"(local), "r"(rank));
    return r;
}
__device__ __forceinline__ void mbar_arrive_remote(uint32_t remAddr) {
    asm volatile("mbarrier.arrive.release.cluster.shared::cluster.b64 _, [%0];"
                 :: "r"(remAddr) : "memory");
}
__device__ __forceinline__ void mbar_wait_cluster(uint32_t mbar, uint32_t parity) {
    uint32_t done = 0;
    while (!done) {
        asm volatile(
            "{\n\t.reg .pred p;\n\t"
            "mbarrier.try_wait.parity.acquire.cluster.shared::cta.b64 p, [%1], %2, 0x989680;\n\t"
            "selp.b32 %0, 1, 0, p;\n\t}"
            : "=r"(done) : "r"(mbar), "r"(parity) : "memory");
    }
}

// ---------------- scratch ----------------
__device__ float g_gx[(size_t)2*L_*1024*B_];          // input gates TRANSPOSED: [2][L][gate-row j][b]
__device__ __nv_bfloat16 g_hb[(size_t)2*L_*B_*H_];    // hidden bf16
__device__ float g_emit[(size_t)L_*B_*T_];
__device__ float g_nll[B_];

// ---------------- input-gate GEMM on HMMA (mma.sync bf16) ----------------
// grid (64 l-groups, 8 j-blocks). jb>>2 = dir, (jb&3)*256 = j offset within dir.
// CTA: stage W block [256 j x 256 k] bf16 once; loop 8 timesteps: gather X[64 b x 256 k] bf16,
// D[256, 64] = W x X^T, bias-fused store to g_gx[d][l][j][b].
static const int IG_PITCH = 528;                 // bytes per smem row (264 halves)
static const int IG_SM_W  = 0;                   // 256 rows
static const int IG_SM_X  = 256 * IG_PITCH;      // 135168; 64 rows
static const int IG_SM_TOK = IG_SM_X + 64 * IG_PITCH;  // 168960
static const int INGATE_SMEM = IG_SM_TOK + 256;

__global__ __launch_bounds__(256, 1) void k_ingate(
    const int* __restrict__ sent, const float* __restrict__ emb,
    const float* __restrict__ Wf, const float* __restrict__ bfv,
    const float* __restrict__ Wb, const float* __restrict__ bbv)
{
    extern __shared__ __align__(1024) char smw[];
    uint32_t smb = smem_u32(smw);
    int* tok = (int*)(smw + IG_SM_TOK);
    int lg = blockIdx.x, jb = blockIdx.y;
    int dir = jb >> 2;
    int jjb = (jb & 3) * 256;
    int tid = threadIdx.x;
    int w = tid >> 5, l = tid & 31;
    const float* W  = dir ? Wb : Wf;
    const float* bv = dir ? bbv : bfv;

    // ---- stage W block to bf16 smem (once) ----
    {
        const float4* Wf4 = (const float4*)(W + (size_t)jjb*256);
        #pragma unroll 4
        for (int i = 0; i < 64; i++) {
            int idx = i*256 + tid;          // 16384 float4
            int r = idx >> 6, c4 = idx & 63;
            float4 v = Wf4[(size_t)r*64 + c4];
            *(uint2*)(smw + IG_SM_W + r*IG_PITCH + c4*8) =
                make_uint2(packbf(v.x, v.y), packbf(v.z, v.w));
        }
    }
    // bias for this thread's output rows (warp w owns m-rows [32w, 32w+32))
    int mb = 32*w;
    int rr0 = mb + (l >> 2);
    float bias[4];
    #pragma unroll
    for (int i = 0; i < 4; i++) bias[i] = bv[jjb + rr0 + 8*i];

    // ldmatrix lane addresses
    uint32_t aAddr[2];
    #pragma unroll
    for (int mt = 0; mt < 2; mt++)
        aAddr[mt] = smb + IG_SM_W + (uint32_t)((mb + mt*16 + (l & 15))*IG_PITCH + (l >> 4)*16);
    uint32_t xAddr[8];
    {
        int lrow = l & 7, grp = l >> 3;
        #pragma unroll
        for (int nt = 0; nt < 8; nt++)
            xAddr[nt] = smb + IG_SM_X + (uint32_t)((nt*8 + lrow)*IG_PITCH + grp*16);
    }
    int cc2 = (l & 3)*2;

    for (int il = 0; il < 8; il++) {
        int lcur = lg*8 + il;
        __syncthreads();                       // Ws ready (il=0) / Xs consumers done (il>0)
        if (tid < 64) tok[tid] = sent[tid*L_ + lcur];
        __syncthreads();
        // ---- stage X (gather + cvt bf16) ----
        #pragma unroll 4
        for (int i = 0; i < 16; i++) {
            int idx = i*256 + tid;             // 4096 float4
            int r = idx >> 6, c4 = idx & 63;
            float4 v = ((const float4*)emb)[(size_t)tok[r]*64 + c4];
            *(uint2*)(smw + IG_SM_X + r*IG_PITCH + c4*8) =
                make_uint2(packbf(v.x, v.y), packbf(v.z, v.w));
        }
        __syncthreads();

        // ---- MMA: D[256,64], warp covers 32 m x 64 n ----
        float acc[2][8][4];
        #pragma unroll
        for (int mt = 0; mt < 2; mt++)
            #pragma unroll
            for (int nt = 0; nt < 8; nt++)
                #pragma unroll
                for (int k = 0; k < 4; k++) acc[mt][nt][k] = 0.f;

        #pragma unroll 2
        for (int ktp = 0; ktp < 8; ktp++) {
            uint32_t af[2][2][4];
            #pragma unroll
            for (int mt = 0; mt < 2; mt++)
                #pragma unroll
                for (int kk = 0; kk < 2; kk++)
                    ldsm_x4(af[mt][kk][0], af[mt][kk][1], af[mt][kk][2], af[mt][kk][3],
                            aAddr[mt] + (ktp*2 + kk)*32);
            #pragma unroll
            for (int nt = 0; nt < 8; nt++) {
                uint32_t b0, b1, b2, b3;
                ldsm_x4(b0, b1, b2, b3, xAddr[nt] + ktp*64);
                #pragma unroll
                for (int mt = 0; mt < 2; mt++) {
                    mma16816(acc[mt][nt][0], acc[mt][nt][1], acc[mt][nt][2], acc[mt][nt][3],
                             af[mt][0][0], af[mt][0][1], af[mt][0][2], af[mt][0][3], b0, b1);
                    mma16816(acc[mt][nt][0], acc[mt][nt][1], acc[mt][nt][2], acc[mt][nt][3],
                             af[mt][1][0], af[mt][1][1], af[mt][1][2], af[mt][1][3], b2, b3);
                }
            }
        }

        // ---- bias + transposed store ----
        float* outb = g_gx + ((size_t)(dir*L_ + lcur)*1024 + jjb)*64;
        #pragma unroll
        for (int mt = 0; mt < 2; mt++) {
            int ra = mb + mt*16 + (l >> 2);
            int rb = ra + 8;
            float ba = bias[mt*2 + 0];
            float bb2 = bias[mt*2 + 1];
            #pragma unroll
            for (int nt = 0; nt < 8; nt++) {
                *(float2*)(outb + (size_t)ra*64 + nt*8 + cc2) =
                    make_float2(acc[mt][nt][0] + ba, acc[mt][nt][1] + ba);
                *(float2*)(outb + (size_t)rb*64 + nt*8 + cc2) =
                    make_float2(acc[mt][nt][2] + bb2, acc[mt][nt][3] + bb2);
            }
        }
    }
}

// ---------------- persistent LSTM: mma.sync, L2 h-exchange, batch-EIGHTH split ----------------
// 128 CTAs = (dir 2) x (batch-eighth 8) x (rank 8). CTA owns hids [32p,32p+32), batches [8be,8be+8).
// D[128 gate-rows, 8 batch] = W_local[128,256] x h_e[8,256]^T
static const int BS_PITCH_B = 528;                    // bytes per B-tile row (8 rows)
static const int SM_PS      = 8 * BS_PITCH_B;         // 4224 (B tile)
static const int PS_PITCH   = 10;                     // floats per Ps row (8 batch + pad)
static const int SM_MBAR    = SM_PS + 128*PS_PITCH*4; // 4224 + 5120 = 9344
static const int LSTM_SMEM  = SM_MBAR + 128;

__global__ __launch_bounds__(256, 1) __cluster_dims__(CS, 1, 1)
void k_lstm(const float* __restrict__ Whf, const float* __restrict__ Whb)
{
    extern __shared__ __align__(1024) char sm[];
    float* Ps = (float*)(sm + SM_PS);
    uint32_t smb = smem_u32(sm);
    int d  = blockIdx.x >> 6;             // direction
    int be = (blockIdx.x >> 3) & 7;       // batch eighth
    uint32_t p;
    asm("mov.u32 %0, %%cluster_ctarank;" : "=r"(p));
    int hb = (int)p * 32;
    int tid = threadIdx.x;
    int w = tid >> 5, l = tid & 31;
    const float* W = d ? Whb : Whf;

    if (tid == 0) {
        asm volatile("mbarrier.init.shared.b64 [%0], %1;" :: "r"(smb + SM_MBAR),     "r"((uint32_t)CS) : "memory");
        asm volatile("mbarrier.init.shared.b64 [%0], %1;" :: "r"(smb + SM_MBAR + 8), "r"((uint32_t)CS) : "memory");
    }
    __syncthreads();
    asm volatile("barrier.cluster.arrive.aligned;" ::: "memory");
    asm volatile("barrier.cluster.wait.aligned;" ::: "memory");

    // ---- A fragments: warp w -> m-rows [16w,16w+16) ----
    int r0 = 16*w + (l >> 2), r1 = r0 + 8;
    const float* wr0 = W + (size_t)((r0 >> 5)*H_ + hb + (r0 & 31))*H_;
    const float* wr1 = W + (size_t)((r1 >> 5)*H_ + hb + (r1 & 31))*H_;
    uint32_t A0[16], A1[16], A2[16], A3[16];
    {
        int kc0 = (l & 3)*2;
        #pragma unroll
        for (int kt = 0; kt < 16; kt++) {
            int kc = kt*16 + kc0;
            A0[kt] = packbf(wr0[kc],   wr0[kc+1]);
            A1[kt] = packbf(wr1[kc],   wr1[kc+1]);
            A2[kt] = packbf(wr0[kc+8], wr0[kc+9]);
            A3[kt] = packbf(wr1[kc+8], wr1[kc+9]);
        }
    }

    // ldmatrix lane row base (single n-tile of 8 local batches)
    uint32_t rowB = smb + (uint32_t)((l & 7)*BS_PITCH_B + (l >> 3)*16);

    // gx accumulator-layout mapping
    int jg0 = (r0 >> 5)*256 + hb + (r0 & 31);
    int jg1 = (r1 >> 5)*256 + hb + (r1 & 31);
    int cc  = (l & 3)*2;

    // phase-B mapping: thread owns exactly one (hid hl, local batch q)
    int hl = tid & 31, q = tid >> 5;
    float cst = 0.f;

    uint32_t rem0 = 0, rem1 = 0;
    if (tid < CS) {
        rem0 = mapa_rank(smb + SM_MBAR,     (uint32_t)tid);
        rem1 = mapa_rank(smb + SM_MBAR + 8, (uint32_t)tid);
    }

    for (int s = 0; s < L_; s++) {
        int t = d ? (L_-1-s) : s;

        // ---- gx prefetch in accumulator layout (independent of h) ----
        float2 gx0, gx1;
        {
            const float* base = g_gx + ((size_t)(d*L_ + t)*1024)*64 + 8*be + cc;
            gx0 = *(const float2*)(base + (size_t)jg0*64);
            gx1 = *(const float2*)(base + (size_t)jg1*64);
        }

        // ---- wait + stage h (bf16 copy, this batch eighth: 4 KB) ----
        if (s == 0) {
            for (int i = tid; i < SM_PS/4; i += 256) ((uint32_t*)sm)[i] = 0;
        } else {
            int sp = s - 1;
            mbar_wait_cluster(smb + SM_MBAR + (sp & 1)*8, (uint32_t)((sp >> 1) & 1));
            int tprev = d ? (t+1) : (t-1);
            const uint4* hsrc = (const uint4*)(g_hb + (((size_t)d*L_ + tprev)*B_ + 8*be)*H_);
            int b = tid >> 5, kq = tid & 31;   // 256 uint4, one per thread
            *(uint4*)(sm + b*BS_PITCH_B + kq*16) = hsrc[tid];
        }
        __syncthreads();

        // ---- MMA mainloop: D[128,8], warp covers 16 m x 8 n ----
        float a0 = 0.f, a1 = 0.f, a2 = 0.f, a3 = 0.f;
        #pragma unroll
        for (int ktp = 0; ktp < 8; ktp++) {
            uint32_t b0, b1, b2, b3;
            ldsm_x4(b0, b1, b2, b3, rowB + ktp*64);
            mma16816(a0, a1, a2, a3, A0[2*ktp],   A1[2*ktp],   A2[2*ktp],   A3[2*ktp],   b0, b1);
            mma16816(a0, a1, a2, a3, A0[2*ktp+1], A1[2*ktp+1], A2[2*ktp+1], A3[2*ktp+1], b2, b3);
        }

        // ---- Ps = D + gx (single store) ----
        *(float2*)(Ps + r0*PS_PITCH + cc) = make_float2(a0 + gx0.x, a1 + gx0.y);
        *(float2*)(Ps + r1*PS_PITCH + cc) = make_float2(a2 + gx1.x, a3 + gx1.y);
        __syncthreads();

        // ---- phase B: activations, c update, h out (bf16) ----
        float hout;
        {
            float vi = Ps[(  0 + hl)*PS_PITCH + q];
            float vf = Ps[( 32 + hl)*PS_PITCH + q];
            float vg = Ps[( 64 + hl)*PS_PITCH + q];
            float vo = Ps[( 96 + hl)*PS_PITCH + q];
            float ig = sigap(vi), fg = sigap(vf), gg = tanhap(vg), og = sigap(vo);
            cst = fg*cst + ig*gg;
            hout = og * tanhap(cst);
        }
        g_hb[(((size_t)d*L_ + t)*B_ + 8*be + q)*H_ + hb + hl] = __float2bfloat16(hout);
        __syncthreads();
        if (tid < CS && s < L_-1) {
            mbar_arrive_remote((s & 1) ? rem1 : rem0);
        }
    }
}

// ---------------- emission GEMM (reads bf16 h; unchanged) ----------------
__global__ __launch_bounds__(768) void k_emit(const float* __restrict__ Wem,
                                              const float* __restrict__ bem)
{
    extern __shared__ float smc[];
    float* Hcat = smc;            // [64][520]
    float* Wsm  = smc + 64*520;   // [12][516]
    int l   = blockIdx.x;
    int tid = threadIdx.x;
    const uint4* hf  = (const uint4*)(g_hb + ((size_t)0*L_ + l)*B_*H_);
    const uint4* hbk = (const uint4*)(g_hb + ((size_t)1*L_ + l)*B_*H_);
    for (int e = tid; e < 2048; e += 768) {
        int r = e >> 5, kq = e & 31;
        uint4 vf = hf[e], vb = hbk[e];
        const __nv_bfloat162* pf = (const __nv_bfloat162*)&vf;
        const __nv_bfloat162* pb = (const __nv_bfloat162*)&vb;
        float* df = Hcat + r*520 + kq*8;
        float* db = Hcat + r*520 + 256 + kq*8;
        #pragma unroll
        for (int qq = 0; qq < 4; qq++) {
            float2 f2 = __bfloat1622float2(pf[qq]);
            float2 b2 = __bfloat1622float2(pb[qq]);
            df[2*qq] = f2.x; df[2*qq+1] = f2.y;
            db[2*qq] = b2.x; db[2*qq+1] = b2.y;
        }
    }
    for (int e = tid; e < 12*512; e += 768)
        Wsm[(e >> 9)*516 + (e & 511)] = Wem[e];
    __syncthreads();

    int b = tid / 12, tg = tid - b*12;
    float acc = bem[tg];
    const float4* hrow = (const float4*)(Hcat + b*520);
    const float4* wrow = (const float4*)(Wsm + tg*516);
    #pragma unroll 8
    for (int k4 = 0; k4 < 128; k4++) {
        float4 x = hrow[k4]; float4 w = wrow[k4];
        acc += w.x*x.x + w.y*x.y + w.z*x.z + w.w*x.w;
    }
    g_emit[((size_t)l*B_ + b)*T_ + tg] = acc;
}

// ---------------- CRF NLL: emissions staged in smem, base-2 scan (unchanged) ----------------
__global__ void k_crf(const int* __restrict__ tags, const float* __restrict__ trans)
{
    __shared__ float se[512*12];
    __shared__ float tr[T_*T_];
    int b = blockIdx.x;
    int lane = threadIdx.x;
    for (int i = lane; i < T_*T_; i += 32) tr[i] = trans[i];
    {
        const float4* src = (const float4*)g_emit;
        float4* dst = (float4*)se;
        for (int i = lane; i < 1536; i += 32) {
            int l = i / 3, j = i - 3*l;
            dst[i] = src[((size_t)l*64 + b)*3 + j];
        }
    }
    __syncwarp();

    const unsigned FULL = 0xffffffffu;
    const float I2 = 1.4426950408889634f;
    const float LN2 = 0.6931471805599453f;
    int mylane = (lane < T_) ? lane : 0;
    float trr2[T_];
    #pragma unroll
    for (int t2 = 0; t2 < T_; t2++) trr2[t2] = tr[t2*T_ + mylane] * I2;

    float a2 = se[mylane] * I2;
    #pragma unroll 4
    for (int l = 1; l < L_; l++) {
        float e2 = se[l*12 + mylane] * I2;
        float v[T_];
        #pragma unroll
        for (int t2 = 0; t2 < T_; t2++)
            v[t2] = __shfl_sync(FULL, a2, t2) + trr2[t2];
        float ex[T_];
        ex[0] = 1.0f;
        #pragma unroll
        for (int t2 = 1; t2 < T_; t2++) ex[t2] = ex2f(v[t2] - v[0]);
        float s01 = ex[0] + ex[1],  s23 = ex[2] + ex[3];
        float s45 = ex[4] + ex[5],  s67 = ex[6] + ex[7];
        float s89 = ex[8] + ex[9],  sAB = ex[10] + ex[11];
        float ssum = ((s01 + s23) + (s45 + s67)) + (s89 + sAB);
        a2 = v[0] + lg2f(ssum) + e2;
    }
    float am = (lane < T_) ? a2 : -1e30f;
    float mm = am;
    for (int o = 16; o; o >>= 1) mm = fmaxf(mm, __shfl_xor_sync(FULL, mm, o));
    float es = (lane < T_) ? ex2f(a2 - mm) : 0.f;
    for (int o = 16; o; o >>= 1) es += __shfl_xor_sync(FULL, es, o);
    float logZ = (mm + lg2f(es)) * LN2;

    float eg = 0.f, tg2 = 0.f;
    for (int l = lane; l < L_; l += 32) {
        int tv = tags[b*L_ + l];
        eg += se[l*12 + tv];
    }
    for (int l = lane; l < L_-1; l += 32) {
        int t0v = tags[b*L_ + l], t1v = tags[b*L_ + l + 1];
        tg2 += tr[t0v*T_ + t1v];
    }
    for (int o = 16; o; o >>= 1) {
        eg  += __shfl_xor_sync(FULL, eg,  o);
        tg2 += __shfl_xor_sync(FULL, tg2, o);
    }
    if (lane == 0) g_nll[b] = logZ - eg - tg2;
}

__global__ void k_mean(float* out)
{
    int lane = threadIdx.x;
    float s = (lane < 32) ? g_nll[lane] + g_nll[lane + 32] : 0.f;
    s += __shfl_xor_sync(0xffffffffu, s, 16);
    s += __shfl_xor_sync(0xffffffffu, s, 8);
    s += __shfl_xor_sync(0xffffffffu, s, 4);
    s += __shfl_xor_sync(0xffffffffu, s, 2);
    s += __shfl_xor_sync(0xffffffffu, s, 1);
    if (lane == 0) out[0] = s / (float)B_;
}

// ---------------- launch ----------------
extern "C" void kernel_launch(void* const* d_in, const int* in_sizes, int n_in,
                              void* d_out, int out_size)
{
    const int*   sent  = (const int*)  d_in[0];
    const int*   tags  = (const int*)  d_in[1];
    const float* emb   = (const float*)d_in[2];
    const float* Wihf  = (const float*)d_in[3];
    const float* Whhf  = (const float*)d_in[4];
    const float* bf    = (const float*)d_in[5];
    const float* Wihb  = (const float*)d_in[6];
    const float* Whhb  = (const float*)d_in[7];
    const float* bb    = (const float*)d_in[8];
    const float* Wem   = (const float*)d_in[9];
    const float* bem   = (const float*)d_in[10];
    const float* trans = (const float*)d_in[11];
    float* out = (float*)d_out;

    cudaFuncSetAttribute(k_ingate, cudaFuncAttributeMaxDynamicSharedMemorySize, INGATE_SMEM);
    cudaFuncSetAttribute(k_lstm,   cudaFuncAttributeMaxDynamicSharedMemorySize, LSTM_SMEM);
    cudaFuncSetAttribute(k_emit,   cudaFuncAttributeMaxDynamicSharedMemorySize, (64*520 + 12*516)*4);

    dim3 gA(64, 8);
    k_ingate<<<gA, 256, INGATE_SMEM>>>(sent, emb, Wihf, bf, Wihb, bb);
    k_lstm<<<128, 256, LSTM_SMEM>>>(Whhf, Whhb);
    k_emit<<<L_, 768, (64*520 + 12*516)*4>>>(Wem, bem);
    k_crf<<<B_, 32>>>(tags, trans);
    k_mean<<<1, 32>>>(out);
}